// round 1
// baseline (speedup 1.0000x reference)
#include <cuda_runtime.h>
#include <math.h>

#define NT        1024
#define MAXITER   20          // supports S up to 20480
#define NFRAMES   6000
#define NTEMPI    60
#define NBEATS    4
#define NTRANS    (NBEATS * NTEMPI)   // 240
#define LTSZ      (NBEATS * NTEMPI * NTEMPI)

// Scratch: __device__ globals (no allocation allowed)
__device__ float          g_dens[NFRAMES * 3];
__device__ int            g_bp[NFRAMES * NTRANS];     // backpointers at first states only
__device__ unsigned short g_scode[NT * MAXITER];      // per-state code: ptr(2b) | isFirst(1b) | firstIdx(8b)

__global__ void dens_kernel(const float* __restrict__ acts) {
    int t = blockIdx.x * blockDim.x + threadIdx.x;
    if (t < NFRAMES) {
        float ab = acts[2 * t];
        float ad = acts[2 * t + 1];
        g_dens[3 * t + 0] = logf((1.0f - ab - ad) / 15.0f);   // OBS_LAMBDA-1 = 15
        g_dens[3 * t + 1] = logf(ab);
        g_dens[3 * t + 2] = logf(ad);
    }
}

__global__ __launch_bounds__(NT, 1)
void viterbi_kernel(const float* __restrict__ log_trans,
                    const int*   __restrict__ prev_last,
                    const int*   __restrict__ first_states,
                    const int*   __restrict__ pointer,
                    float*       __restrict__ out,
                    int S, int out_size)
{
    extern __shared__ float sm[];
    float* vA    = sm;                  // S floats
    float* vB    = vA + S;              // S floats
    float* ltT   = vB + S;              // LTSZ floats, transposed: ltT[b][j][i] = log_trans[b][i][j]
    float* sCand = ltT + LTSZ;          // 256
    float* sBest = sCand + 256;         // 256
    float* sDens = sBest + 256;         // 8
    float* rv    = sDens + 8;           // NT
    int*   ri    = (int*)(rv + NT);     // NT
    int*   sPrev = ri + NT;             // 256

    const int tid = threadIdx.x;

    // ---------------- init ----------------
    float v0 = -logf((float)S);
    for (int s = tid; s < S; s += NT) {
        vA[s] = v0;
        g_scode[s] = (unsigned short)(pointer[s] & 3);
    }
    for (int idx = tid; idx < LTSZ; idx += NT) {
        int b = idx / (NTEMPI * NTEMPI);
        int r = (idx - b * NTEMPI * NTEMPI) / NTEMPI;   // i
        int c = idx % NTEMPI;                           // j
        ltT[b * NTEMPI * NTEMPI + c * NTEMPI + r] = log_trans[idx];
    }
    if (tid < NTRANS) sPrev[tid] = prev_last[tid];
    __syncthreads();
    if (tid < NTRANS) {
        int s = first_states[tid];
        g_scode[s] |= (unsigned short)(4u | ((unsigned)tid << 3));
    }
    __syncthreads();

    // hoist per-state codes into registers (static over the whole frame loop)
    unsigned code[MAXITER];
    #pragma unroll
    for (int k = 0; k < MAXITER; k++) {
        int s = tid + k * NT;
        code[k] = (s < S) ? (unsigned)g_scode[s] : 0u;
    }

    const int b60 = tid / NTEMPI;          // only meaningful for tid < 240
    const int i60 = tid - b60 * NTEMPI;

    // ---------------- 6000 sequential Viterbi steps ----------------
    for (int t = 0; t < NFRAMES; t++) {
        const float* vO = (t & 1) ? vB : vA;
        float*       vN = (t & 1) ? vA : vB;

        // Phase A1: gather candidate values at previous-beat last states; fetch dens row
        if (tid < NTRANS) {
            sCand[tid] = vO[sPrev[tid]];
        } else if (tid < NTRANS + 3) {
            sDens[tid - NTRANS] = g_dens[3 * t + (tid - NTRANS)];
        }
        __syncthreads();

        // Phase A2: 60-way max/argmax per (beat, tempo); first-index tie-break matches argmax
        if (tid < NTRANS) {
            const float* c  = sCand + b60 * NTEMPI;
            const float* lt = ltT + b60 * NTEMPI * NTEMPI + i60;
            float best = -3.0e38f;
            int   arg  = 0;
            #pragma unroll
            for (int j = 0; j < NTEMPI; j++) {
                float sc = c[j] + lt[j * NTEMPI];
                if (sc > best) { best = sc; arg = j; }
            }
            sBest[tid] = best;
            g_bp[t * NTRANS + tid] = sPrev[b60 * NTEMPI + arg];
        }
        __syncthreads();

        // Phase B: shift + observation add over all S states
        float d0 = sDens[0], d1 = sDens[1], d2 = sDens[2];
        #pragma unroll
        for (int k = 0; k < MAXITER; k++) {
            int s = tid + k * NT;
            if (s < S) {
                unsigned cd = code[k];
                float val = (cd & 4u) ? sBest[cd >> 3] : vO[s - 1];  // s==0 is always a first state
                unsigned p = cd & 3u;
                float d = (p == 0u) ? d0 : ((p == 1u) ? d1 : d2);
                vN[s] = val + d;
            }
        }
        __syncthreads();
    }

    // Final v is in vA (last write at odd t=5999 targeted vA)
    const float* vF = vA;

    // ---------------- argmax(v_final), first-index tie-break ----------------
    float bv = -3.0e38f;
    int   bi = 0x7FFFFFFF;
    for (int s = tid; s < S; s += NT) {
        float x = vF[s];
        if (x > bv) { bv = x; bi = s; }   // strided ascending => strict '>' keeps smallest idx in-thread
    }
    rv[tid] = bv; ri[tid] = bi;
    __syncthreads();
    for (int off = NT / 2; off > 0; off >>= 1) {
        if (tid < off) {
            float xv = rv[tid + off]; int xi = ri[tid + off];
            if (xv > rv[tid] || (xv == rv[tid] && xi < ri[tid])) { rv[tid] = xv; ri[tid] = xi; }
        }
        __syncthreads();
    }

    // ---------------- backtrace (thread 0) ----------------
    if (tid == 0) {
        int s = ri[0];
        float logp = rv[0];
        if (out_size > NFRAMES) out[NFRAMES] = logp;
        out[NFRAMES - 1] = (float)s;
        for (int t = NFRAMES - 1; t >= 1; t--) {
            unsigned cd = (unsigned)g_scode[s];
            int p = (cd & 4u) ? g_bp[t * NTRANS + (int)(cd >> 3)] : (s - 1);
            out[t - 1] = (float)p;
            s = p;
        }
    }
}

extern "C" void kernel_launch(void* const* d_in, const int* in_sizes, int n_in,
                              void* d_out, int out_size) {
    const float* acts         = (const float*)d_in[0];
    const float* log_trans    = (const float*)d_in[1];
    const int*   prev_last    = (const int*)d_in[2];
    const int*   first_states = (const int*)d_in[3];
    const int*   pointer      = (const int*)d_in[4];
    int S = in_sizes[4];   // pointer has one entry per state

    size_t smem_floats = (size_t)(2 * S) + LTSZ + 256 + 256 + 8 + NT;
    size_t smem_ints   = (size_t)NT + 256;
    size_t smem = (smem_floats + smem_ints) * sizeof(float);

    cudaFuncSetAttribute(viterbi_kernel, cudaFuncAttributeMaxDynamicSharedMemorySize, (int)smem);

    dens_kernel<<<(NFRAMES + 255) / 256, 256>>>(acts);
    viterbi_kernel<<<1, NT, smem>>>(log_trans, prev_last, first_states, pointer,
                                    (float*)d_out, S, out_size);
}

// round 2
// speedup vs baseline: 2.2470x; 2.2470x over previous
#include <cuda_runtime.h>
#include <math.h>

#define NT        1024
#define NFRAMES   6000
#define NTEMPI    60
#define NBEATS    4
#define NTRANS    (NBEATS * NTEMPI)     // 240
#define LT_STRIDE 61
#define LT2SZ     (NBEATS * NTEMPI * LT_STRIDE)   // 14640
#define CH        20                    // states per bulk thread
#define NBULK     768                   // threads 256..1023
#define SPAD      (NBULK * CH)          // 15360 padded state count
#define FIXCAP    1536

// -------- smem layout (floats) --------
// [0 .. SPAD+3]                vA physical (vA = sm+4, states 0..SPAD-1)
// [SPAD+4 .. 2*SPAD+7]         vB physical (vB = sm+SPAD+8)
#define OFF_LT2   (2 * SPAD + 8)
#define OFF_CAND  (OFF_LT2 + LT2SZ)
#define OFF_PREV  (OFF_CAND + 256)
#define OFF_FIX   (OFF_PREV + 256)
#define OFF_NFIX  (OFF_FIX + FIXCAP)
#define OFF_RV    (OFF_NFIX + 4)
#define OFF_RI    (OFF_RV + NT)
#define SMEM_FLOATS (OFF_RI + NT)
#define SMEM_BYTES  (SMEM_FLOATS * 4)

__device__ float g_dens[NFRAMES * 3];
__device__ int   g_bp[NFRAMES * NTRANS];

__global__ void dens_kernel(const float* __restrict__ acts) {
    int t = blockIdx.x * blockDim.x + threadIdx.x;
    if (t < NFRAMES) {
        float ab = acts[2 * t];
        float ad = acts[2 * t + 1];
        g_dens[3 * t + 0] = logf((1.0f - ab - ad) / 15.0f);
        g_dens[3 * t + 1] = logf(ab);
        g_dens[3 * t + 2] = logf(ad);
    }
}

__global__ __launch_bounds__(NT, 1)
void viterbi_kernel(const float* __restrict__ log_trans,
                    const int*   __restrict__ prev_last,
                    const int*   __restrict__ first_states,
                    const int*   __restrict__ pointer,
                    float*       __restrict__ out,
                    int S, int out_size)
{
    extern __shared__ float sm[];
    float* vA    = sm + 4;
    float* vB    = sm + SPAD + 8;
    float* lt2   = sm + OFF_LT2;                 // [b][i][j], stride 61
    float* sCand = sm + OFF_CAND;
    int*   sPrev = (int*)(sm + OFF_PREV);
    int*   fixL  = (int*)(sm + OFF_FIX);
    int*   nFixP = (int*)(sm + OFF_NFIX);
    float* rv    = sm + OFF_RV;
    int*   ri    = (int*)(sm + OFF_RI);

    const int tid = threadIdx.x;

    // ================= init =================
    if (tid == 0) *nFixP = 0;
    float v0 = -logf((float)S);
    for (int s = tid; s < SPAD; s += NT) vA[s] = v0;

    // lt2: transposed-to-row layout with pad-61 (conflict-free scalar LDS)
    for (int idx = tid; idx < NBEATS * NTEMPI * NTEMPI; idx += NT) {
        int b = idx / (NTEMPI * NTEMPI);
        int r = (idx - b * NTEMPI * NTEMPI) / NTEMPI;
        int c = idx % NTEMPI;
        lt2[b * NTEMPI * LT_STRIDE + r * LT_STRIDE + c] = log_trans[idx];
    }
    if (tid < NTRANS) sPrev[tid] = prev_last[tid];

    // mark first states using vB as int scratch (vB rewritten at t=0 anyway)
    int* mark = (int*)vB;
    for (int s = tid; s < SPAD; s += NT) mark[s] = 0;
    __syncthreads();
    int firstS = 0;
    if (tid < NTRANS) {
        firstS = first_states[tid];
        mark[firstS] = 1;
    }
    __syncthreads();
    // fix list: non-first states with ptr != 0
    for (int s = tid; s < S; s += NT) {
        int p = pointer[s];
        if (p != 0 && mark[s] == 0) {
            int idx = atomicAdd(nFixP, 1);
            if (idx < FIXCAP) fixL[idx] = s | ((p - 1) << 14);
        }
    }
    __syncthreads();
    const int nFix = *nFixP;

    // A-thread statics: beat/tempo split, finite-transition window
    int b60 = 0, i60 = 0, lo = 0, hi = 0;
    float dFirstIs2 = 0.0f;
    if (tid < NTRANS) {
        b60 = tid / NTEMPI;
        i60 = tid - b60 * NTEMPI;
        dFirstIs2 = (b60 == 0) ? 1.0f : 0.0f;
        const float* row = lt2 + b60 * NTEMPI * LT_STRIDE + i60 * LT_STRIDE;
        lo = NTEMPI; hi = -1;
        for (int j = 0; j < NTEMPI; j++) {
            if (row[j] > -1e29f) { if (j < lo) lo = j; hi = j; }
        }
    }
    __syncthreads();

    const int u  = tid - 256;          // bulk thread index
    const int s0 = u * CH;

    float* vO = vA;
    float* vN = vB;

    // ================= 6000 Viterbi steps =================
    for (int t = 0; t < NFRAMES; t++) {
        float d0 = g_dens[3 * t + 0];
        float d1 = g_dens[3 * t + 1];
        float d2 = g_dens[3 * t + 2];

        __syncthreads();   // sync1: vO fully valid (prev fix done)

        float bestReg = 0.0f;
        if (tid < 256) {
            // ---- Phase A: 240 threads, concurrent with bulk ----
            if (tid < NTRANS) sCand[tid] = vO[sPrev[tid]];
            asm volatile("bar.sync 1, 256;" ::: "memory");
            if (tid < NTRANS) {
                const float* c   = sCand + b60 * NTEMPI;
                const float* row = lt2 + b60 * NTEMPI * LT_STRIDE + i60 * LT_STRIDE;
                float best = -3.0e38f;
                int   arg  = lo;
                for (int j = lo; j <= hi; j++) {
                    float sc = c[j] + row[j];
                    if (sc > best) { best = sc; arg = j; }
                }
                g_bp[t * NTRANS + tid] = sPrev[b60 * NTEMPI + arg];
                bestReg = best;
            }
        } else {
            // ---- Phase B bulk: vN[s] = vO[s-1] + d0, vectorized ----
            const float4* src = (const float4*)(vO + s0 - 4);
            float4*       dst = (float4*)(vN + s0);
            float carry = src[0].w;
            #pragma unroll
            for (int j = 1; j <= CH / 4; j++) {
                float4 L = src[j];
                float4 o;
                o.x = carry + d0;
                o.y = L.x + d0;
                o.z = L.y + d0;
                o.w = L.z + d0;
                dst[j - 1] = o;
                carry = L.w;
            }
        }

        __syncthreads();   // sync2: bulk writes done

        // ---- fix pass: overwrite ptr!=0 states and first states ----
        if (tid < NTRANS) {
            vN[firstS] = bestReg + (dFirstIs2 != 0.0f ? d2 : d1);
        }
        for (int e = tid; e < nFix; e += NT) {
            int c = fixL[e];
            int s = c & 0x3FFF;
            vN[s] = vO[s - 1] + ((c >> 14) ? d2 : d1);
        }

        float* tmp = vO; vO = vN; vN = tmp;
    }
    __syncthreads();
    const float* vF = vO;   // after swap, vO holds the final v

    // ================= argmax(v_final), first-index tie-break =================
    float bv = -3.0e38f;
    int   bi = 0x7FFFFFFF;
    for (int s = tid; s < S; s += NT) {
        float x = vF[s];
        if (x > bv) { bv = x; bi = s; }
    }
    rv[tid] = bv; ri[tid] = bi;
    __syncthreads();
    for (int off = NT / 2; off > 0; off >>= 1) {
        if (tid < off) {
            float xv = rv[tid + off]; int xi = ri[tid + off];
            if (xv > rv[tid] || (xv == rv[tid] && xi < ri[tid])) { rv[tid] = xv; ri[tid] = xi; }
        }
        __syncthreads();
    }

    // ================= backtrace =================
    // sFidx overlays lt2 (no longer needed)
    short* sFidx = (short*)lt2;
    for (int s = tid; s < SPAD; s += NT) sFidx[s] = -1;
    __syncthreads();
    if (tid < NTRANS) sFidx[firstS] = (short)tid;
    __syncthreads();

    if (tid == 0) {
        int s = ri[0];
        if (out_size > NFRAMES) out[NFRAMES] = rv[0];
        out[NFRAMES - 1] = (float)s;
        for (int t = NFRAMES - 1; t >= 1; t--) {
            short f = sFidx[s];
            int p = (f >= 0) ? g_bp[t * NTRANS + f] : (s - 1);
            out[t - 1] = (float)p;
            s = p;
        }
    }
}

extern "C" void kernel_launch(void* const* d_in, const int* in_sizes, int n_in,
                              void* d_out, int out_size) {
    const float* acts         = (const float*)d_in[0];
    const float* log_trans    = (const float*)d_in[1];
    const int*   prev_last    = (const int*)d_in[2];
    const int*   first_states = (const int*)d_in[3];
    const int*   pointer      = (const int*)d_in[4];
    int S = in_sizes[4];

    cudaFuncSetAttribute(viterbi_kernel, cudaFuncAttributeMaxDynamicSharedMemorySize, SMEM_BYTES);

    dens_kernel<<<(NFRAMES + 255) / 256, 256>>>(acts);
    viterbi_kernel<<<1, NT, SMEM_BYTES>>>(log_trans, prev_last, first_states, pointer,
                                          (float*)d_out, S, out_size);
}